// round 11
// baseline (speedup 1.0000x reference)
#include <cuda_runtime.h>
#include <cuda_fp16.h>
#include <math.h>

#define DIM    1024
#define PAR    8
#define NN     255          // nodes per tree
#define WIDTH  2040         // PAR * NN
#define DEPTH  7
#define NSTEP  (DEPTH + 1)  // 8 visited nodes per tree
#define NACT   (PAR * NSTEP) // 64 active nodes per row
#define MAXB   8192          // max rows (4*2048)

// Static scratch (no dynamic allocation allowed):
__device__ __half g_WoutT_h[WIDTH * DIM];        // transposed W_out, fp16 (4.2MB)
__device__ float  g_act[MAXB * NACT];            // stage-1 activations (2MB)
__device__ int    g_leaf[MAXB * PAR];            // depth-7 leaf per (row,tree)

// ---------------------------------------------------------------------------
// Kernel 1: transpose W_out [DIM, WIDTH] -> g_WoutT_h [WIDTH, DIM], fp32->fp16.
// ---------------------------------------------------------------------------
__global__ __launch_bounds__(256) void transpose_wout(const float* __restrict__ Wout) {
    __shared__ __half tile[32][33];
    const int tx = threadIdx.x, ty = threadIdx.y;
    const int w0 = blockIdx.x * 32, d0 = blockIdx.y * 32;
    const int w  = w0 + tx;
    #pragma unroll
    for (int k = 0; k < 4; ++k) {
        const int d = d0 + ty + 8 * k;
        if (w < WIDTH)
            tile[ty + 8 * k][tx] = __float2half_rn(Wout[(size_t)d * WIDTH + w]);
    }
    __syncthreads();
    #pragma unroll
    for (int k = 0; k < 4; ++k) {
        const int ww = w0 + ty + 8 * k;
        if (ww < WIDTH)
            g_WoutT_h[(size_t)ww * DIM + d0 + tx] = tile[tx][ty + 8 * k];
    }
}

// ---------------------------------------------------------------------------
// Kernel 2: stage 1 — tree descent, split-D layout.
// 256 threads per row = 4 pairs of warps. Pair p drives trees p and p+4
// (ILP-2); within a pair, warp half h owns dims [h*512, h*512+512).
// Halves combine via a 2-float smem exchange + named barrier (64 threads),
// double-buffered on step parity. Decisions in exact fp32.
// ---------------------------------------------------------------------------
__global__ __launch_bounds__(256) void fff_stage1(
    const float* __restrict__ x,
    const float* __restrict__ Win,
    const float* __restrict__ bin)
{
    __shared__ float s_part[4][2][2][2];   // [pair][parity][half][tree]

    const int row  = blockIdx.x;
    const int warp = threadIdx.x >> 5;     // 0..7
    const int lane = threadIdx.x & 31;
    const int pair = warp >> 1;            // 0..3
    const int h    = warp & 1;             // dim half
    const int t0   = pair;                 // first tree
    const int t1   = pair + 4;             // second tree
    const int joff = h * 128 + lane;       // float4 index base into 1024-dim row

    // Lane's fixed slice of x: 16 floats (4x float4).
    const float4* __restrict__ xg = (const float4*)(x + (size_t)row * DIM);
    float4 xr[4];
    #pragma unroll
    for (int k = 0; k < 4; ++k) xr[k] = __ldg(xg + joff + 32 * k);

    int cur0 = 0, cur1 = 0;                // node index within each tree

    float* __restrict__ act0 = g_act + (size_t)row * NACT + t0 * NSTEP;
    float* __restrict__ act1 = g_act + (size_t)row * NACT + t1 * NSTEP;

    #pragma unroll 1
    for (int step = 0; step < NSTEP; ++step) {
        const int w0 = t0 * NN + cur0;
        const int w1 = t1 * NN + cur1;
        const float4* __restrict__ Wr0 = (const float4*)(Win + (size_t)w0 * DIM);
        const float4* __restrict__ Wr1 = (const float4*)(Win + (size_t)w1 * DIM);

        float a0 = 0.f, b0 = 0.f, a1 = 0.f, b1 = 0.f;
        #pragma unroll
        for (int k = 0; k < 4; ++k) {      // 16 floats / lane / tree
            const float4 v0 = __ldg(Wr0 + joff + 32 * k);
            const float4 v1 = __ldg(Wr1 + joff + 32 * k);
            a0 += v0.x * xr[k].x + v0.y * xr[k].y;
            b0 += v0.z * xr[k].z + v0.w * xr[k].w;
            a1 += v1.x * xr[k].x + v1.y * xr[k].y;
            b1 += v1.z * xr[k].z + v1.w * xr[k].w;
        }
        float s0 = a0 + b0;
        float s1 = a1 + b1;
        #pragma unroll
        for (int off = 16; off; off >>= 1) {   // two interleaved butterflies
            s0 += __shfl_xor_sync(0xffffffffu, s0, off);
            s1 += __shfl_xor_sync(0xffffffffu, s1, off);
        }

        const int par = step & 1;
        if (lane == 0) {
            s_part[pair][par][h][0] = s0;
            s_part[pair][par][h][1] = s1;
        }
        asm volatile("bar.sync %0, 64;" :: "r"(pair + 1) : "memory");

        // Both warps of the pair form identical totals (same order, same bits).
        const float l0 = (s_part[pair][par][0][0] + s_part[pair][par][1][0])
                         + __ldg(bin + w0);
        const float l1 = (s_part[pair][par][0][1] + s_part[pair][par][1][1])
                         + __ldg(bin + w1);

        if (h == 0 && lane == 0) {
            act0[step] = l0 / (1.f + expf(-l0));   // silu
            act1[step] = l1 / (1.f + expf(-l1));
        }
        cur0 = 2 * cur0 + 1 + (l0 > 0.f ? 1 : 0);
        cur1 = 2 * cur1 + 1 + (l1 > 0.f ? 1 : 0);
    }

    if (h == 0 && lane == 0) {
        g_leaf[row * PAR + t0] = (cur0 - 1) >> 1;  // depth-7 node (127..254)
        g_leaf[row * PAR + t1] = (cur1 - 1) >> 1;
    }
}

// ---------------------------------------------------------------------------
// Kernel 3: stage 2 — out[row] = sum_i act_i * W_outT[node_i, :].
// fp16 weights, fp32 accumulate. 128 threads; thread t owns dims 8t..8t+7.
// Node indices reconstructed from the depth-7 leaf (path = prefixes of leaf).
// ---------------------------------------------------------------------------
__global__ __launch_bounds__(128) void fff_stage2(float* __restrict__ out)
{
    __shared__ float s_a[NACT];
    __shared__ int   s_w[NACT];

    const int row = blockIdx.x;
    const int tid = threadIdx.x;

    if (tid < NACT) {
        s_a[tid] = g_act[(size_t)row * NACT + tid];
        const int tree = tid >> 3;
        const int step = tid & 7;
        const int leaf = g_leaf[row * PAR + tree];      // heap idx at depth 7
        s_w[tid] = tree * NN + (((leaf + 1) >> (7 - step)) - 1);
    }
    __syncthreads();

    float acc[8];
    #pragma unroll
    for (int j = 0; j < 8; ++j) acc[j] = 0.f;

    #pragma unroll 8
    for (int i = 0; i < NACT; ++i) {
        const float a = s_a[i];
        const uint4 u = *((const uint4*)(g_WoutT_h + (size_t)s_w[i] * DIM) + tid);
        const __half2* h = (const __half2*)&u;
        #pragma unroll
        for (int j = 0; j < 4; ++j) {
            const float2 f = __half22float2(h[j]);
            acc[2 * j]     += a * f.x;
            acc[2 * j + 1] += a * f.y;
        }
    }

    float4* op = (float4*)(out + (size_t)row * DIM) + 2 * tid;
    float4 r0; r0.x = acc[0]; r0.y = acc[1]; r0.z = acc[2]; r0.w = acc[3];
    float4 r1; r1.x = acc[4]; r1.y = acc[5]; r1.z = acc[6]; r1.w = acc[7];
    op[0] = r0;
    op[1] = r1;
}

// ---------------------------------------------------------------------------
extern "C" void kernel_launch(void* const* d_in, const int* in_sizes, int n_in,
                              void* d_out, int out_size) {
    const float* oldx  = (const float*)d_in[0];   // [4,2048,1024] f32
    const float* W_in  = (const float*)d_in[1];   // [2040,1024] f32
    const float* b_in  = (const float*)d_in[2];   // [2040] f32
    const float* W_out = (const float*)d_in[3];   // [1024,2040] f32
    float* out = (float*)d_out;

    const int B = in_sizes[0] / DIM;              // 8192 rows

    transpose_wout<<<dim3((WIDTH + 31) / 32, DIM / 32), dim3(32, 8)>>>(W_out);
    fff_stage1<<<B, 256>>>(oldx, W_in, b_in);
    fff_stage2<<<B, 128>>>(out);
}

// round 12
// speedup vs baseline: 1.1763x; 1.1763x over previous
#include <cuda_runtime.h>
#include <cuda_fp16.h>
#include <math.h>

#define DIM    1024
#define PAR    8
#define NN     255          // nodes per tree
#define WIDTH  2040         // PAR * NN
#define DEPTH  7
#define NSTEP  (DEPTH + 1)  // 8 visited nodes per tree
#define NACT   (PAR * NSTEP) // 64 active nodes per row
#define MAXB   8192          // max rows (4*2048)

// Static scratch (no dynamic allocation allowed):
__device__ __half g_WoutT_h[WIDTH * DIM];        // transposed W_out, fp16 (4.2MB)
__device__ float  g_act[MAXB * NACT];            // stage-1 activations (2MB)
__device__ int    g_leaf[MAXB * PAR];            // depth-7 leaf per (row,tree)

// ---------------------------------------------------------------------------
// Kernel 1: transpose W_out [DIM, WIDTH] -> g_WoutT_h [WIDTH, DIM], fp32->fp16.
// ---------------------------------------------------------------------------
__global__ __launch_bounds__(256) void transpose_wout(const float* __restrict__ Wout) {
    __shared__ __half tile[32][33];
    const int tx = threadIdx.x, ty = threadIdx.y;
    const int w0 = blockIdx.x * 32, d0 = blockIdx.y * 32;
    const int w  = w0 + tx;
    #pragma unroll
    for (int k = 0; k < 4; ++k) {
        const int d = d0 + ty + 8 * k;
        if (w < WIDTH)
            tile[ty + 8 * k][tx] = __float2half_rn(Wout[(size_t)d * WIDTH + w]);
    }
    __syncthreads();
    #pragma unroll
    for (int k = 0; k < 4; ++k) {
        const int ww = w0 + ty + 8 * k;
        if (ww < WIDTH)
            g_WoutT_h[(size_t)ww * DIM + d0 + tx] = tile[tx][ty + 8 * k];
    }
}

// ---------------------------------------------------------------------------
// Kernel 2: stage 1 — tree descent. 128 threads per row; each of the 4 warps
// drives TWO trees interleaved (independent ILP-2 chains sharing one
// register-resident x slice). No intra-step barriers. Bias is folded into
// lane 0's partial BEFORE the butterfly so its load overlaps the dot.
// Decisions in exact fp32.
// ---------------------------------------------------------------------------
__global__ __launch_bounds__(128, 6) void fff_stage1(
    const float* __restrict__ x,
    const float* __restrict__ Win,
    const float* __restrict__ bin)
{
    const int row  = blockIdx.x;
    const int warp = threadIdx.x >> 5;   // 0..3
    const int lane = threadIdx.x & 31;
    const int t0   = warp;               // first tree
    const int t1   = warp + 4;           // second tree

    // Lane's fixed slice of x: elements 4*(lane+32k)..+3, k=0..7 (32 floats).
    const float4* __restrict__ xg = (const float4*)(x + (size_t)row * DIM);
    float4 xr[8];
    #pragma unroll
    for (int k = 0; k < 8; ++k) xr[k] = __ldg(xg + lane + 32 * k);

    int cur0 = 0, cur1 = 0;              // node index within each tree

    float* __restrict__ act0 = g_act + (size_t)row * NACT + t0 * NSTEP;
    float* __restrict__ act1 = g_act + (size_t)row * NACT + t1 * NSTEP;

    #pragma unroll 1
    for (int step = 0; step < NSTEP; ++step) {
        const int w0 = t0 * NN + cur0;
        const int w1 = t1 * NN + cur1;
        const float4* __restrict__ Wr0 = (const float4*)(Win + (size_t)w0 * DIM);
        const float4* __restrict__ Wr1 = (const float4*)(Win + (size_t)w1 * DIM);

        // Bias folded into lane 0's partial: load issues here, retires under
        // the FMA tree, and the post-reduce FADD disappears from the chain.
        float a0 = (lane == 0) ? __ldg(bin + w0) : 0.f;
        float a1 = (lane == 0) ? __ldg(bin + w1) : 0.f;
        float b0 = 0.f, b1 = 0.f;
        #pragma unroll
        for (int k = 0; k < 8; ++k) {
            const float4 v0 = __ldg(Wr0 + lane + 32 * k);
            const float4 v1 = __ldg(Wr1 + lane + 32 * k);
            a0 += v0.x * xr[k].x + v0.y * xr[k].y;
            b0 += v0.z * xr[k].z + v0.w * xr[k].w;
            a1 += v1.x * xr[k].x + v1.y * xr[k].y;
            b1 += v1.z * xr[k].z + v1.w * xr[k].w;
        }
        float l0 = a0 + b0;
        float l1 = a1 + b1;
        #pragma unroll
        for (int off = 16; off; off >>= 1) {    // two interleaved butterflies
            l0 += __shfl_xor_sync(0xffffffffu, l0, off);
            l1 += __shfl_xor_sync(0xffffffffu, l1, off);
        }
        if (lane == 0) {
            act0[step] = l0 / (1.f + expf(-l0));   // silu
            act1[step] = l1 / (1.f + expf(-l1));
        }
        cur0 = 2 * cur0 + 1 + (l0 > 0.f ? 1 : 0);
        cur1 = 2 * cur1 + 1 + (l1 > 0.f ? 1 : 0);
    }

    if (lane == 0) {
        g_leaf[row * PAR + t0] = (cur0 - 1) >> 1;  // depth-7 node (127..254)
        g_leaf[row * PAR + t1] = (cur1 - 1) >> 1;
    }
}

// ---------------------------------------------------------------------------
// Kernel 3: stage 2 — out[row] = sum_i act_i * W_outT[node_i, :].
// fp16 weights, fp32 accumulate. 128 threads; thread t owns dims 8t..8t+7.
// Node indices reconstructed from the depth-7 leaf (path = prefixes of leaf).
// ---------------------------------------------------------------------------
__global__ __launch_bounds__(128) void fff_stage2(float* __restrict__ out)
{
    __shared__ float s_a[NACT];
    __shared__ int   s_w[NACT];

    const int row = blockIdx.x;
    const int tid = threadIdx.x;

    if (tid < NACT) {
        s_a[tid] = g_act[(size_t)row * NACT + tid];
        const int tree = tid >> 3;
        const int step = tid & 7;
        const int leaf = g_leaf[row * PAR + tree];      // heap idx at depth 7
        s_w[tid] = tree * NN + (((leaf + 1) >> (7 - step)) - 1);
    }
    __syncthreads();

    float acc[8];
    #pragma unroll
    for (int j = 0; j < 8; ++j) acc[j] = 0.f;

    #pragma unroll 8
    for (int i = 0; i < NACT; ++i) {
        const float a = s_a[i];
        const uint4 u = *((const uint4*)(g_WoutT_h + (size_t)s_w[i] * DIM) + tid);
        const __half2* h = (const __half2*)&u;
        #pragma unroll
        for (int j = 0; j < 4; ++j) {
            const float2 f = __half22float2(h[j]);
            acc[2 * j]     += a * f.x;
            acc[2 * j + 1] += a * f.y;
        }
    }

    float4* op = (float4*)(out + (size_t)row * DIM) + 2 * tid;
    float4 r0; r0.x = acc[0]; r0.y = acc[1]; r0.z = acc[2]; r0.w = acc[3];
    float4 r1; r1.x = acc[4]; r1.y = acc[5]; r1.z = acc[6]; r1.w = acc[7];
    op[0] = r0;
    op[1] = r1;
}

// ---------------------------------------------------------------------------
extern "C" void kernel_launch(void* const* d_in, const int* in_sizes, int n_in,
                              void* d_out, int out_size) {
    const float* oldx  = (const float*)d_in[0];   // [4,2048,1024] f32
    const float* W_in  = (const float*)d_in[1];   // [2040,1024] f32
    const float* b_in  = (const float*)d_in[2];   // [2040] f32
    const float* W_out = (const float*)d_in[3];   // [1024,2040] f32
    float* out = (float*)d_out;

    const int B = in_sizes[0] / DIM;              // 8192 rows

    transpose_wout<<<dim3((WIDTH + 31) / 32, DIM / 32), dim3(32, 8)>>>(W_out);
    fff_stage1<<<B, 128>>>(oldx, W_in, b_in);
    fff_stage2<<<B, 128>>>(out);
}

// round 15
// speedup vs baseline: 1.1784x; 1.0018x over previous
#include <cuda_runtime.h>
#include <cuda_fp16.h>
#include <math.h>

#define DIM    1024
#define PAR    8
#define NN     255          // nodes per tree
#define WIDTH  2040         // PAR * NN
#define DEPTH  7
#define NSTEP  (DEPTH + 1)  // 8 visited nodes per tree
#define NACT   (PAR * NSTEP) // 64 active nodes per row
#define MAXB   8192          // max rows (4*2048)

// Static scratch (no dynamic allocation allowed):
__device__ __half g_WoutT_h[WIDTH * DIM];        // transposed W_out, fp16 (4.2MB)
__device__ float  g_act[MAXB * NACT];            // stage-1 activations (2MB)
__device__ int    g_leaf[MAXB * PAR];            // depth-7 leaf per (row,tree)

// ---------------------------------------------------------------------------
// Kernel 1: transpose W_out [DIM, WIDTH] -> g_WoutT_h [WIDTH, DIM], fp32->fp16.
// ---------------------------------------------------------------------------
__global__ __launch_bounds__(256) void transpose_wout(const float* __restrict__ Wout) {
    __shared__ __half tile[32][33];
    const int tx = threadIdx.x, ty = threadIdx.y;
    const int w0 = blockIdx.x * 32, d0 = blockIdx.y * 32;
    const int w  = w0 + tx;
    #pragma unroll
    for (int k = 0; k < 4; ++k) {
        const int d = d0 + ty + 8 * k;
        if (w < WIDTH)
            tile[ty + 8 * k][tx] = __float2half_rn(Wout[(size_t)d * WIDTH + w]);
    }
    __syncthreads();
    #pragma unroll
    for (int k = 0; k < 4; ++k) {
        const int ww = w0 + ty + 8 * k;
        if (ww < WIDTH)
            g_WoutT_h[(size_t)ww * DIM + d0 + tx] = tile[tx][ty + 8 * k];
    }
}

// ---------------------------------------------------------------------------
// Kernel 2: stage 1 — tree descent, ILP-4. 64 threads per row (2 warps);
// each warp drives FOUR trees interleaved. The four descent chains are
// fully independent (no barriers — R11 lesson) and share one
// register-resident x slice. Four butterflies pipeline their SHFLs.
// Decisions in exact fp32 (identical to reference).
// ---------------------------------------------------------------------------
__global__ __launch_bounds__(64, 8) void fff_stage1(
    const float* __restrict__ x,
    const float* __restrict__ Win,
    const float* __restrict__ bin)
{
    const int row  = blockIdx.x;
    const int warp = threadIdx.x >> 5;   // 0..1
    const int lane = threadIdx.x & 31;
    const int tb   = warp * 4;           // this warp's trees: tb..tb+3

    // Lane's fixed slice of x: elements 4*(lane+32k)..+3, k=0..7 (32 floats).
    const float4* __restrict__ xg = (const float4*)(x + (size_t)row * DIM);
    float4 xr[8];
    #pragma unroll
    for (int k = 0; k < 8; ++k) xr[k] = __ldg(xg + lane + 32 * k);

    int cur[4] = {0, 0, 0, 0};           // node index within each tree

    #pragma unroll 1
    for (int step = 0; step < NSTEP; ++step) {
        int wrow[4];
        const float4* __restrict__ Wr[4];
        #pragma unroll
        for (int j = 0; j < 4; ++j) {
            wrow[j] = (tb + j) * NN + cur[j];
            Wr[j]   = (const float4*)(Win + (size_t)wrow[j] * DIM);
        }

        // Bias folded into lane 0's partial: its load overlaps the dot.
        float accA[4], accB[4];
        #pragma unroll
        for (int j = 0; j < 4; ++j) {
            accA[j] = (lane == 0) ? __ldg(bin + wrow[j]) : 0.f;
            accB[j] = 0.f;
        }

        #pragma unroll
        for (int k = 0; k < 8; ++k) {          // 32 floats / lane / tree
            #pragma unroll
            for (int j = 0; j < 4; ++j) {
                const float4 v = __ldg(Wr[j] + lane + 32 * k);
                accA[j] += v.x * xr[k].x + v.y * xr[k].y;
                accB[j] += v.z * xr[k].z + v.w * xr[k].w;
            }
        }

        float s[4];
        #pragma unroll
        for (int j = 0; j < 4; ++j) s[j] = accA[j] + accB[j];

        // Four interleaved butterflies: 20 SHFLs pipeline in-warp.
        #pragma unroll
        for (int off = 16; off; off >>= 1) {
            #pragma unroll
            for (int j = 0; j < 4; ++j)
                s[j] += __shfl_xor_sync(0xffffffffu, s[j], off);
        }

        if (lane == 0) {
            #pragma unroll
            for (int j = 0; j < 4; ++j) {
                const float l = s[j];
                g_act[(size_t)row * NACT + (tb + j) * NSTEP + step]
                    = l / (1.f + expf(-l));        // silu
            }
        }
        #pragma unroll
        for (int j = 0; j < 4; ++j)
            cur[j] = 2 * cur[j] + 1 + (s[j] > 0.f ? 1 : 0);
    }

    if (lane == 0) {
        #pragma unroll
        for (int j = 0; j < 4; ++j)
            g_leaf[row * PAR + tb + j] = (cur[j] - 1) >> 1;  // depth-7 node
    }
}

// ---------------------------------------------------------------------------
// Kernel 3: stage 2 — out[row] = sum_i act_i * W_outT[node_i, :].
// fp16 weights, fp32 accumulate. 128 threads; thread t owns dims 8t..8t+7.
// Node indices reconstructed from the depth-7 leaf (path = prefixes of leaf).
// ---------------------------------------------------------------------------
__global__ __launch_bounds__(128) void fff_stage2(float* __restrict__ out)
{
    __shared__ float s_a[NACT];
    __shared__ int   s_w[NACT];

    const int row = blockIdx.x;
    const int tid = threadIdx.x;

    if (tid < NACT) {
        s_a[tid] = g_act[(size_t)row * NACT + tid];
        const int tree = tid >> 3;
        const int step = tid & 7;
        const int leaf = g_leaf[row * PAR + tree];      // heap idx at depth 7
        s_w[tid] = tree * NN + (((leaf + 1) >> (7 - step)) - 1);
    }
    __syncthreads();

    float acc[8];
    #pragma unroll
    for (int j = 0; j < 8; ++j) acc[j] = 0.f;

    #pragma unroll 8
    for (int i = 0; i < NACT; ++i) {
        const float a = s_a[i];
        const uint4 u = *((const uint4*)(g_WoutT_h + (size_t)s_w[i] * DIM) + tid);
        const __half2* h = (const __half2*)&u;
        #pragma unroll
        for (int j = 0; j < 4; ++j) {
            const float2 f = __half22float2(h[j]);
            acc[2 * j]     += a * f.x;
            acc[2 * j + 1] += a * f.y;
        }
    }

    float4* op = (float4*)(out + (size_t)row * DIM) + 2 * tid;
    float4 r0; r0.x = acc[0]; r0.y = acc[1]; r0.z = acc[2]; r0.w = acc[3];
    float4 r1; r1.x = acc[4]; r1.y = acc[5]; r1.z = acc[6]; r1.w = acc[7];
    op[0] = r0;
    op[1] = r1;
}

// ---------------------------------------------------------------------------
extern "C" void kernel_launch(void* const* d_in, const int* in_sizes, int n_in,
                              void* d_out, int out_size) {
    const float* oldx  = (const float*)d_in[0];   // [4,2048,1024] f32
    const float* W_in  = (const float*)d_in[1];   // [2040,1024] f32
    const float* b_in  = (const float*)d_in[2];   // [2040] f32
    const float* W_out = (const float*)d_in[3];   // [1024,2040] f32
    float* out = (float*)d_out;

    const int B = in_sizes[0] / DIM;              // 8192 rows

    transpose_wout<<<dim3((WIDTH + 31) / 32, DIM / 32), dim3(32, 8)>>>(W_out);
    fff_stage1<<<B, 64>>>(oldx, W_in, b_in);
    fff_stage2<<<B, 128>>>(out);
}

// round 16
// speedup vs baseline: 1.2543x; 1.0644x over previous
#include <cuda_runtime.h>
#include <cuda_fp16.h>
#include <math.h>

#define DIM    1024
#define PAR    8
#define NN     255          // nodes per tree
#define WIDTH  2040         // PAR * NN
#define DEPTH  7
#define NSTEP  (DEPTH + 1)  // 8 visited nodes per tree
#define NACT   (PAR * NSTEP) // 64 active nodes per row
#define MAXB   8192          // max rows (4*2048)
#define TAU    0.015f        // fp16-logit guard band (strict err bound ~1.25e-2)

// Static scratch (no dynamic allocation allowed):
__device__ __half g_WoutT_h[WIDTH * DIM];        // transposed W_out, fp16 (4.2MB)
__device__ __half g_Win_h[WIDTH * DIM];          // W_in, fp16, same layout (4.2MB)
__device__ float  g_act[MAXB * NACT];            // stage-1 activations (2MB)
__device__ int    g_leaf[MAXB * PAR];            // depth-7 leaf per (row,tree)

// ---------------------------------------------------------------------------
// Kernel 0: W_in fp32 -> fp16 copy (same layout).
// ---------------------------------------------------------------------------
__global__ __launch_bounds__(256) void convert_win(const float* __restrict__ Win) {
    const int i = blockIdx.x * 256 + threadIdx.x;       // one uint4 (8 halves)
    const float4 a = __ldg((const float4*)Win + 2 * i);
    const float4 b = __ldg((const float4*)Win + 2 * i + 1);
    __half2 h[4];
    h[0] = __floats2half2_rn(a.x, a.y);
    h[1] = __floats2half2_rn(a.z, a.w);
    h[2] = __floats2half2_rn(b.x, b.y);
    h[3] = __floats2half2_rn(b.z, b.w);
    ((uint4*)g_Win_h)[i] = *(const uint4*)h;
}

// ---------------------------------------------------------------------------
// Kernel 1: transpose W_out [DIM, WIDTH] -> g_WoutT_h [WIDTH, DIM], fp32->fp16.
// ---------------------------------------------------------------------------
__global__ __launch_bounds__(256) void transpose_wout(const float* __restrict__ Wout) {
    __shared__ __half tile[32][33];
    const int tx = threadIdx.x, ty = threadIdx.y;
    const int w0 = blockIdx.x * 32, d0 = blockIdx.y * 32;
    const int w  = w0 + tx;
    #pragma unroll
    for (int k = 0; k < 4; ++k) {
        const int d = d0 + ty + 8 * k;
        if (w < WIDTH)
            tile[ty + 8 * k][tx] = __float2half_rn(Wout[(size_t)d * WIDTH + w]);
    }
    __syncthreads();
    #pragma unroll
    for (int k = 0; k < 4; ++k) {
        const int ww = w0 + ty + 8 * k;
        if (ww < WIDTH)
            g_WoutT_h[(size_t)ww * DIM + d0 + tx] = tile[tx][ty + 8 * k];
    }
}

// Full-warp butterfly reduce (all lanes end with the sum).
__device__ __forceinline__ float warp_sum(float v) {
    #pragma unroll
    for (int off = 16; off; off >>= 1)
        v += __shfl_xor_sync(0xffffffffu, v, off);
    return v;
}

// ---------------------------------------------------------------------------
// Kernel 2: stage 1 — tree descent, fp16 weights + exact-decision fallback.
// 128 threads per row; each of the 4 warps drives TWO trees (ILP-2,
// independent chains, no barriers). Lane owns x floats 8*lane+256k..+7
// (k=0..3) so each fp16 weight chunk is one coalesced uint4 (8 halves).
// If |logit_fp16| < TAU, the node is recomputed with fp32 weights, making
// every decision provably equal to the fp32 traversal.
// ---------------------------------------------------------------------------
__global__ __launch_bounds__(128, 6) void fff_stage1(
    const float* __restrict__ x,
    const float* __restrict__ Win,
    const float* __restrict__ bin)
{
    const int row  = blockIdx.x;
    const int warp = threadIdx.x >> 5;   // 0..3
    const int lane = threadIdx.x & 31;
    const int t0   = warp;               // first tree
    const int t1   = warp + 4;           // second tree

    // x slice: floats [8*lane + 256k, +8), k=0..3 -> xr[2k], xr[2k+1].
    const float4* __restrict__ xg = (const float4*)(x + (size_t)row * DIM);
    float4 xr[8];
    #pragma unroll
    for (int k = 0; k < 4; ++k) {
        xr[2 * k]     = __ldg(xg + 2 * lane + 64 * k);
        xr[2 * k + 1] = __ldg(xg + 2 * lane + 64 * k + 1);
    }

    int cur0 = 0, cur1 = 0;              // node index within each tree

    float* __restrict__ act0 = g_act + (size_t)row * NACT + t0 * NSTEP;
    float* __restrict__ act1 = g_act + (size_t)row * NACT + t1 * NSTEP;

    #pragma unroll 1
    for (int step = 0; step < NSTEP; ++step) {
        const int w0 = t0 * NN + cur0;
        const int w1 = t1 * NN + cur1;
        const float bl0 = __ldg(bin + w0);           // uniform; overlaps dot
        const float bl1 = __ldg(bin + w1);
        const uint4* __restrict__ Wh0 = (const uint4*)(g_Win_h + (size_t)w0 * DIM);
        const uint4* __restrict__ Wh1 = (const uint4*)(g_Win_h + (size_t)w1 * DIM);

        float a0 = 0.f, b0 = 0.f, a1 = 0.f, b1 = 0.f;
        #pragma unroll
        for (int k = 0; k < 4; ++k) {                // 32 halves / lane / tree
            const uint4 u0 = __ldg(Wh0 + lane + 32 * k);
            const uint4 u1 = __ldg(Wh1 + lane + 32 * k);
            const __half2* h0 = (const __half2*)&u0;
            const __half2* h1 = (const __half2*)&u1;
            const float2 p00 = __half22float2(h0[0]);
            const float2 p01 = __half22float2(h0[1]);
            const float2 p02 = __half22float2(h0[2]);
            const float2 p03 = __half22float2(h0[3]);
            const float2 p10 = __half22float2(h1[0]);
            const float2 p11 = __half22float2(h1[1]);
            const float2 p12 = __half22float2(h1[2]);
            const float2 p13 = __half22float2(h1[3]);
            a0 += p00.x * xr[2*k].x   + p00.y * xr[2*k].y;
            b0 += p01.x * xr[2*k].z   + p01.y * xr[2*k].w;
            a0 += p02.x * xr[2*k+1].x + p02.y * xr[2*k+1].y;
            b0 += p03.x * xr[2*k+1].z + p03.y * xr[2*k+1].w;
            a1 += p10.x * xr[2*k].x   + p10.y * xr[2*k].y;
            b1 += p11.x * xr[2*k].z   + p11.y * xr[2*k].w;
            a1 += p12.x * xr[2*k+1].x + p12.y * xr[2*k+1].y;
            b1 += p13.x * xr[2*k+1].z + p13.y * xr[2*k+1].w;
        }
        float l0 = warp_sum(a0 + b0) + bl0;
        float l1 = warp_sum(a1 + b1) + bl1;

        // Guard band: recompute with fp32 weights if the fp16 logit is too
        // close to zero to trust the sign. Warp-uniform branch, P ~ 2%.
        if (fabsf(l0) < TAU) {
            const float4* __restrict__ W32 = (const float4*)(Win + (size_t)w0 * DIM);
            float p = 0.f, q = 0.f;
            #pragma unroll
            for (int k = 0; k < 4; ++k) {
                const float4 v = __ldg(W32 + 2 * lane + 64 * k);
                const float4 u = __ldg(W32 + 2 * lane + 64 * k + 1);
                p += v.x * xr[2*k].x   + v.y * xr[2*k].y;
                q += v.z * xr[2*k].z   + v.w * xr[2*k].w;
                p += u.x * xr[2*k+1].x + u.y * xr[2*k+1].y;
                q += u.z * xr[2*k+1].z + u.w * xr[2*k+1].w;
            }
            l0 = warp_sum(p + q) + bl0;
        }
        if (fabsf(l1) < TAU) {
            const float4* __restrict__ W32 = (const float4*)(Win + (size_t)w1 * DIM);
            float p = 0.f, q = 0.f;
            #pragma unroll
            for (int k = 0; k < 4; ++k) {
                const float4 v = __ldg(W32 + 2 * lane + 64 * k);
                const float4 u = __ldg(W32 + 2 * lane + 64 * k + 1);
                p += v.x * xr[2*k].x   + v.y * xr[2*k].y;
                q += v.z * xr[2*k].z   + v.w * xr[2*k].w;
                p += u.x * xr[2*k+1].x + u.y * xr[2*k+1].y;
                q += u.z * xr[2*k+1].z + u.w * xr[2*k+1].w;
            }
            l1 = warp_sum(p + q) + bl1;
        }

        if (lane == 0) {
            act0[step] = l0 / (1.f + expf(-l0));   // silu
            act1[step] = l1 / (1.f + expf(-l1));
        }
        cur0 = 2 * cur0 + 1 + (l0 > 0.f ? 1 : 0);
        cur1 = 2 * cur1 + 1 + (l1 > 0.f ? 1 : 0);
    }

    if (lane == 0) {
        g_leaf[row * PAR + t0] = (cur0 - 1) >> 1;  // depth-7 node (127..254)
        g_leaf[row * PAR + t1] = (cur1 - 1) >> 1;
    }
}

// ---------------------------------------------------------------------------
// Kernel 3: stage 2 — out[row] = sum_i act_i * W_outT[node_i, :].
// fp16 weights, fp32 accumulate. 128 threads; thread t owns dims 8t..8t+7.
// Node indices reconstructed from the depth-7 leaf (path = prefixes of leaf).
// ---------------------------------------------------------------------------
__global__ __launch_bounds__(128) void fff_stage2(float* __restrict__ out)
{
    __shared__ float s_a[NACT];
    __shared__ int   s_w[NACT];

    const int row = blockIdx.x;
    const int tid = threadIdx.x;

    if (tid < NACT) {
        s_a[tid] = g_act[(size_t)row * NACT + tid];
        const int tree = tid >> 3;
        const int step = tid & 7;
        const int leaf = g_leaf[row * PAR + tree];      // heap idx at depth 7
        s_w[tid] = tree * NN + (((leaf + 1) >> (7 - step)) - 1);
    }
    __syncthreads();

    float acc[8];
    #pragma unroll
    for (int j = 0; j < 8; ++j) acc[j] = 0.f;

    #pragma unroll 8
    for (int i = 0; i < NACT; ++i) {
        const float a = s_a[i];
        const uint4 u = *((const uint4*)(g_WoutT_h + (size_t)s_w[i] * DIM) + tid);
        const __half2* h = (const __half2*)&u;
        #pragma unroll
        for (int j = 0; j < 4; ++j) {
            const float2 f = __half22float2(h[j]);
            acc[2 * j]     += a * f.x;
            acc[2 * j + 1] += a * f.y;
        }
    }

    float4* op = (float4*)(out + (size_t)row * DIM) + 2 * tid;
    float4 r0; r0.x = acc[0]; r0.y = acc[1]; r0.z = acc[2]; r0.w = acc[3];
    float4 r1; r1.x = acc[4]; r1.y = acc[5]; r1.z = acc[6]; r1.w = acc[7];
    op[0] = r0;
    op[1] = r1;
}

// ---------------------------------------------------------------------------
extern "C" void kernel_launch(void* const* d_in, const int* in_sizes, int n_in,
                              void* d_out, int out_size) {
    const float* oldx  = (const float*)d_in[0];   // [4,2048,1024] f32
    const float* W_in  = (const float*)d_in[1];   // [2040,1024] f32
    const float* b_in  = (const float*)d_in[2];   // [2040] f32
    const float* W_out = (const float*)d_in[3];   // [1024,2040] f32
    float* out = (float*)d_out;

    const int B = in_sizes[0] / DIM;              // 8192 rows

    convert_win<<<(WIDTH * DIM / 8 + 255) / 256, 256>>>(W_in);
    transpose_wout<<<dim3((WIDTH + 31) / 32, DIM / 32), dim3(32, 8)>>>(W_out);
    fff_stage1<<<B, 128>>>(oldx, W_in, b_in);
    fff_stage2<<<B, 128>>>(out);
}

// round 17
// speedup vs baseline: 1.3298x; 1.0603x over previous
#include <cuda_runtime.h>
#include <cuda_fp16.h>
#include <math.h>

#define DIM    1024
#define PAR    8
#define NN     255          // nodes per tree
#define WIDTH  2040         // PAR * NN
#define DEPTH  7
#define NSTEP  (DEPTH + 1)  // 8 visited nodes per tree
#define NACT   (PAR * NSTEP) // 64 active nodes per row
#define MAXB   8192          // max rows (4*2048)
#define TAU    0.015f        // fp16-logit guard band (strict err bound ~1.25e-2)

#define CONV_BLOCKS 1020    // convert_win blocks: 1020*256 uint4 = WIDTH*DIM/8
#define TRAN_BX 64          // transpose tiles in width dim (64*32 >= 2040)
#define TRAN_BY 32          // transpose tiles in dim dim (32*32 = 1024)

// Static scratch (no dynamic allocation allowed):
__device__ __half g_WoutT_h[WIDTH * DIM];        // transposed W_out, fp16 (4.2MB)
__device__ __half g_Win_h[WIDTH * DIM];          // W_in, fp16, same layout (4.2MB)
__device__ float  g_act[MAXB * NACT];            // stage-1 activations (2MB)
__device__ int    g_leaf[MAXB * PAR];            // depth-7 leaf per (row,tree)

// ---------------------------------------------------------------------------
// Kernel 0: fused prep. blocks [0, CONV_BLOCKS): W_in fp32->fp16 copy.
// blocks [CONV_BLOCKS, +TRAN_BX*TRAN_BY): W_out transpose+convert.
// The two jobs are independent; one launch removes serialization.
// ---------------------------------------------------------------------------
__global__ __launch_bounds__(256) void prep_weights(
    const float* __restrict__ Win, const float* __restrict__ Wout)
{
    const int bid = blockIdx.x;
    const int tid = threadIdx.x;

    if (bid < CONV_BLOCKS) {
        const int i = bid * 256 + tid;               // one uint4 (8 halves)
        const float4 a = __ldg((const float4*)Win + 2 * i);
        const float4 b = __ldg((const float4*)Win + 2 * i + 1);
        __half2 h[4];
        h[0] = __floats2half2_rn(a.x, a.y);
        h[1] = __floats2half2_rn(a.z, a.w);
        h[2] = __floats2half2_rn(b.x, b.y);
        h[3] = __floats2half2_rn(b.z, b.w);
        ((uint4*)g_Win_h)[i] = *(const uint4*)h;
    } else {
        __shared__ __half tile[32][33];
        const int b2 = bid - CONV_BLOCKS;
        const int w0 = (b2 % TRAN_BX) * 32;
        const int d0 = (b2 / TRAN_BX) * 32;
        const int tx = tid & 31, ty = tid >> 5;      // 32 x 8
        const int w  = w0 + tx;
        #pragma unroll
        for (int k = 0; k < 4; ++k) {
            const int d = d0 + ty + 8 * k;
            if (w < WIDTH)
                tile[ty + 8 * k][tx] = __float2half_rn(Wout[(size_t)d * WIDTH + w]);
        }
        __syncthreads();
        #pragma unroll
        for (int k = 0; k < 4; ++k) {
            const int ww = w0 + ty + 8 * k;
            if (ww < WIDTH)
                g_WoutT_h[(size_t)ww * DIM + d0 + tx] = tile[tx][ty + 8 * k];
        }
    }
}

// ---------------------------------------------------------------------------
// Kernel 2: stage 1 — tree descent, ILP-4 on fp16 weights.
// 64 threads per row (2 warps); each warp drives FOUR trees interleaved
// (independent chains, no barriers). Lane owns x floats 8*lane+256k..+7
// so each fp16 weight chunk is one coalesced uint4 (8 halves).
// Guard band: if |logit_fp16| < TAU, recompute that node with fp32
// weights -> decisions provably equal to the fp32 traversal.
// ---------------------------------------------------------------------------
__global__ __launch_bounds__(64, 10) void fff_stage1(
    const float* __restrict__ x,
    const float* __restrict__ Win,
    const float* __restrict__ bin)
{
    const int row  = blockIdx.x;
    const int warp = threadIdx.x >> 5;   // 0..1
    const int lane = threadIdx.x & 31;
    const int tb   = warp * 4;           // this warp's trees: tb..tb+3

    // x slice: floats [8*lane + 256k, +8), k=0..3 -> xr[2k], xr[2k+1].
    const float4* __restrict__ xg = (const float4*)(x + (size_t)row * DIM);
    float4 xr[8];
    #pragma unroll
    for (int k = 0; k < 4; ++k) {
        xr[2 * k]     = __ldg(xg + 2 * lane + 64 * k);
        xr[2 * k + 1] = __ldg(xg + 2 * lane + 64 * k + 1);
    }

    int cur[4] = {0, 0, 0, 0};           // node index within each tree

    #pragma unroll 1
    for (int step = 0; step < NSTEP; ++step) {
        int wrow[4];
        float bl[4];
        #pragma unroll
        for (int j = 0; j < 4; ++j) {
            wrow[j] = (tb + j) * NN + cur[j];
            bl[j]   = __ldg(bin + wrow[j]);          // uniform; overlaps dot
        }

        float sA[4] = {0.f, 0.f, 0.f, 0.f};
        float sB[4] = {0.f, 0.f, 0.f, 0.f};
        #pragma unroll
        for (int k = 0; k < 4; ++k) {                // 32 halves / lane / tree
            #pragma unroll
            for (int j = 0; j < 4; ++j) {
                const uint4 u =
                    __ldg((const uint4*)(g_Win_h + (size_t)wrow[j] * DIM) + lane + 32 * k);
                const __half2* h = (const __half2*)&u;
                const float2 p0 = __half22float2(h[0]);
                const float2 p1 = __half22float2(h[1]);
                const float2 p2 = __half22float2(h[2]);
                const float2 p3 = __half22float2(h[3]);
                sA[j] += p0.x * xr[2*k].x   + p0.y * xr[2*k].y;
                sB[j] += p1.x * xr[2*k].z   + p1.y * xr[2*k].w;
                sA[j] += p2.x * xr[2*k+1].x + p2.y * xr[2*k+1].y;
                sB[j] += p3.x * xr[2*k+1].z + p3.y * xr[2*k+1].w;
            }
        }

        float l[4];
        #pragma unroll
        for (int j = 0; j < 4; ++j) l[j] = sA[j] + sB[j];

        // Four interleaved butterflies: SHFLs pipeline in-warp.
        #pragma unroll
        for (int off = 16; off; off >>= 1) {
            #pragma unroll
            for (int j = 0; j < 4; ++j)
                l[j] += __shfl_xor_sync(0xffffffffu, l[j], off);
        }
        #pragma unroll
        for (int j = 0; j < 4; ++j) l[j] += bl[j];

        // Guard band: rare warp-uniform fallback to exact fp32 dot.
        #pragma unroll
        for (int j = 0; j < 4; ++j) {
            if (fabsf(l[j]) < TAU) {
                const float4* __restrict__ W32 =
                    (const float4*)(Win + (size_t)wrow[j] * DIM);
                float p = 0.f, q = 0.f;
                #pragma unroll
                for (int k = 0; k < 4; ++k) {
                    const float4 v = __ldg(W32 + 2 * lane + 64 * k);
                    const float4 u = __ldg(W32 + 2 * lane + 64 * k + 1);
                    p += v.x * xr[2*k].x   + v.y * xr[2*k].y;
                    q += v.z * xr[2*k].z   + v.w * xr[2*k].w;
                    p += u.x * xr[2*k+1].x + u.y * xr[2*k+1].y;
                    q += u.z * xr[2*k+1].z + u.w * xr[2*k+1].w;
                }
                float s = p + q;
                #pragma unroll
                for (int off = 16; off; off >>= 1)
                    s += __shfl_xor_sync(0xffffffffu, s, off);
                l[j] = s + bl[j];
            }
        }

        if (lane == 0) {
            #pragma unroll
            for (int j = 0; j < 4; ++j)
                g_act[(size_t)row * NACT + (tb + j) * NSTEP + step]
                    = l[j] / (1.f + expf(-l[j]));    // silu
        }
        #pragma unroll
        for (int j = 0; j < 4; ++j)
            cur[j] = 2 * cur[j] + 1 + (l[j] > 0.f ? 1 : 0);
    }

    if (lane == 0) {
        #pragma unroll
        for (int j = 0; j < 4; ++j)
            g_leaf[row * PAR + tb + j] = (cur[j] - 1) >> 1;  // depth-7 node
    }
}

// ---------------------------------------------------------------------------
// Kernel 3: stage 2 — out[row] = sum_i act_i * W_outT[node_i, :].
// fp16 weights, fp32 accumulate. 128 threads; thread t owns dims 8t..8t+7.
// Chunked: 8 (act, node) pairs hoisted to registers per chunk so the 8
// weight LDG.128s issue back-to-back.
// ---------------------------------------------------------------------------
__global__ __launch_bounds__(128, 12) void fff_stage2(float* __restrict__ out)
{
    __shared__ float s_a[NACT];
    __shared__ int   s_w[NACT];

    const int row = blockIdx.x;
    const int tid = threadIdx.x;

    if (tid < NACT) {
        s_a[tid] = g_act[(size_t)row * NACT + tid];
        const int tree = tid >> 3;
        const int step = tid & 7;
        const int leaf = g_leaf[row * PAR + tree];      // heap idx at depth 7
        s_w[tid] = tree * NN + (((leaf + 1) >> (7 - step)) - 1);
    }
    __syncthreads();

    float acc[8];
    #pragma unroll
    for (int j = 0; j < 8; ++j) acc[j] = 0.f;

    #pragma unroll 1
    for (int c = 0; c < NACT; c += 8) {
        float a[8]; int w[8];
        #pragma unroll
        for (int j = 0; j < 8; ++j) { a[j] = s_a[c + j]; w[j] = s_w[c + j]; }

        #pragma unroll
        for (int j = 0; j < 8; ++j) {
            const uint4 u = *((const uint4*)(g_WoutT_h + (size_t)w[j] * DIM) + tid);
            const __half2* h = (const __half2*)&u;
            #pragma unroll
            for (int m = 0; m < 4; ++m) {
                const float2 f = __half22float2(h[m]);
                acc[2 * m]     += a[j] * f.x;
                acc[2 * m + 1] += a[j] * f.y;
            }
        }
    }

    float4* op = (float4*)(out + (size_t)row * DIM) + 2 * tid;
    float4 r0; r0.x = acc[0]; r0.y = acc[1]; r0.z = acc[2]; r0.w = acc[3];
    float4 r1; r1.x = acc[4]; r1.y = acc[5]; r1.z = acc[6]; r1.w = acc[7];
    op[0] = r0;
    op[1] = r1;
}

// ---------------------------------------------------------------------------
extern "C" void kernel_launch(void* const* d_in, const int* in_sizes, int n_in,
                              void* d_out, int out_size) {
    const float* oldx  = (const float*)d_in[0];   // [4,2048,1024] f32
    const float* W_in  = (const float*)d_in[1];   // [2040,1024] f32
    const float* b_in  = (const float*)d_in[2];   // [2040] f32
    const float* W_out = (const float*)d_in[3];   // [1024,2040] f32
    float* out = (float*)d_out;

    const int B = in_sizes[0] / DIM;              // 8192 rows

    prep_weights<<<CONV_BLOCKS + TRAN_BX * TRAN_BY, 256>>>(W_in, W_out);
    fff_stage1<<<B, 64>>>(oldx, W_in, b_in);
    fff_stage2<<<B, 128>>>(out);
}